// round 13
// baseline (speedup 1.0000x reference)
#include <cuda_runtime.h>
#include <cuda_bf16.h>
#include <cuda_fp16.h>
#include <cstdint>

// Problem dims
#define V_ 32000
#define E_ 1024
#define H_ 1024
#define B_ 32
#define T_ 128
#define M_ (B_ * T_)          // 4096

// Output layout in d_out
#define OUT_HID  ((size_t)M_ * V_)
#define OUT_LAST (OUT_HID + 2ULL * B_ * H_)

typedef unsigned long long ull;
typedef __nv_bfloat16 bf16;

// ---------------- scratch (device globals) ----------------
__device__ float g_bufA[M_ * H_];
__device__ float g_bufB[M_ * H_];
__device__ float g_hbuf[2][B_ * H_];
__device__ ull   g_acnt = 0;
__device__ ull   g_gen  = 0;

__device__ bf16 g_Ahi[(size_t)M_ * H_];      // proj A splits (bf16)
__device__ bf16 g_Alo[(size_t)M_ * H_];
__device__ bf16 g_Phi[(size_t)H_ * H_];      // proj W splits (bf16)
__device__ bf16 g_Plo[(size_t)H_ * H_];
__device__ half g_Wh16[(size_t)V_ * H_];     // W_out fp16
__device__ half g_Ah16[(size_t)M_ * H_];     // output-A fp16

// ---------------- helpers ----------------
__device__ __forceinline__ void ffma2(ull& c, ull a, ull b) {
    asm("fma.rn.f32x2 %0, %1, %2, %0;" : "+l"(c) : "l"(a), "l"(b));
}
__device__ __forceinline__ float2 unpack2(ull v) {
    float2 r; asm("mov.b64 {%0, %1}, %2;" : "=f"(r.x), "=f"(r.y) : "l"(v)); return r;
}
__device__ __forceinline__ uint32_t smem_u32(const void* p) {
    uint32_t a;
    asm("{ .reg .u64 t; cvta.to.shared.u64 t, %1; cvt.u32.u64 %0, t; }" : "=r"(a) : "l"(p));
    return a;
}
__device__ __forceinline__ void cpa16(uint32_t d, const void* s) {
    asm volatile("cp.async.cg.shared.global [%0], [%1], 16;" :: "r"(d), "l"(s));
}
#define CP_COMMIT() asm volatile("cp.async.commit_group;" ::: "memory")
#define CP_WAIT0()  asm volatile("cp.async.wait_group 0;" ::: "memory")
#define CP_WAIT1()  asm volatile("cp.async.wait_group 1;" ::: "memory")
#define CP_WAIT2()  asm volatile("cp.async.wait_group 2;" ::: "memory")
#define CP_WAIT3()  asm volatile("cp.async.wait_group 3;" ::: "memory")

__device__ __forceinline__ void ldsm4(uint32_t& r0, uint32_t& r1, uint32_t& r2, uint32_t& r3,
                                      uint32_t addr) {
    asm volatile("ldmatrix.sync.aligned.m8n8.x4.shared.b16 {%0,%1,%2,%3}, [%4];"
                 : "=r"(r0), "=r"(r1), "=r"(r2), "=r"(r3) : "r"(addr));
}
__device__ __forceinline__ void mma_bf(float* c, const uint32_t* a, const uint32_t* b) {
    asm volatile(
        "mma.sync.aligned.m16n8k16.row.col.f32.bf16.bf16.f32 "
        "{%0,%1,%2,%3}, {%4,%5,%6,%7}, {%8,%9}, {%0,%1,%2,%3};"
        : "+f"(c[0]), "+f"(c[1]), "+f"(c[2]), "+f"(c[3])
        : "r"(a[0]), "r"(a[1]), "r"(a[2]), "r"(a[3]), "r"(b[0]), "r"(b[1]));
}
__device__ __forceinline__ void mma_fp(float* c, const uint32_t* a, const uint32_t* b) {
    asm volatile(
        "mma.sync.aligned.m16n8k16.row.col.f32.f16.f16.f32 "
        "{%0,%1,%2,%3}, {%4,%5,%6,%7}, {%8,%9}, {%0,%1,%2,%3};"
        : "+f"(c[0]), "+f"(c[1]), "+f"(c[2]), "+f"(c[3])
        : "r"(a[0]), "r"(a[1]), "r"(a[2]), "r"(a[3]), "r"(b[0]), "r"(b[1]));
}

// ============================================================================
// Conversion kernels
// ============================================================================
__global__ void split_bf(const float* __restrict__ src,
                         bf16* __restrict__ hi, bf16* __restrict__ lo)
{
    size_t i = ((size_t)blockIdx.x * 256 + threadIdx.x) * 4;
    float4 v = *(const float4*)(src + i);
    union { bf16 h[4]; uint2 u; } H, L;
    float vv[4] = {v.x, v.y, v.z, v.w};
    #pragma unroll
    for (int j = 0; j < 4; j++) {
        bf16 h = __float2bfloat16_rn(vv[j]);
        H.h[j] = h;
        L.h[j] = __float2bfloat16_rn(vv[j] - __bfloat162float(h));
    }
    *(uint2*)(hi + i) = H.u;
    *(uint2*)(lo + i) = L.u;
}

__global__ void split_gather_bf(const float* __restrict__ emb, const int* __restrict__ tok,
                                bf16* __restrict__ hi, bf16* __restrict__ lo)
{
    int m = blockIdx.x;
    int row = tok[m];
    size_t s = (size_t)row * H_ + threadIdx.x * 4;
    size_t d = (size_t)m * H_ + threadIdx.x * 4;
    float4 v = *(const float4*)(emb + s);
    union { bf16 h[4]; uint2 u; } H, L;
    float vv[4] = {v.x, v.y, v.z, v.w};
    #pragma unroll
    for (int j = 0; j < 4; j++) {
        bf16 h = __float2bfloat16_rn(vv[j]);
        H.h[j] = h;
        L.h[j] = __float2bfloat16_rn(vv[j] - __bfloat162float(h));
    }
    *(uint2*)(hi + d) = H.u;
    *(uint2*)(lo + d) = L.u;
}

__global__ void conv_f16(const float* __restrict__ src, half* __restrict__ dst)
{
    size_t i = ((size_t)blockIdx.x * 256 + threadIdx.x) * 8;
    float4 v0 = *(const float4*)(src + i);
    float4 v1 = *(const float4*)(src + i + 4);
    union { half h[8]; uint4 u; } O;
    O.h[0] = __float2half_rn(v0.x); O.h[1] = __float2half_rn(v0.y);
    O.h[2] = __float2half_rn(v0.z); O.h[3] = __float2half_rn(v0.w);
    O.h[4] = __float2half_rn(v1.x); O.h[5] = __float2half_rn(v1.y);
    O.h[6] = __float2half_rn(v1.z); O.h[7] = __float2half_rn(v1.w);
    *(uint4*)(dst + i) = O.u;
}

// ============================================================================
// Shared GEMM pieces: 128x128 tile, K-chunk 32, row = 64 B of 16-bit elems
// ============================================================================
__device__ __forceinline__ uint32_t sw_addr(uint32_t tile, int row, int chunk) {
    return tile + (uint32_t)row * 64u + (uint32_t)((chunk ^ ((row >> 1) & 3)) * 16);
}
#define TILE_B 8192u
#define NCC 32

// ---------------- bf16 3-term projection GEMM (1 CTA/SM) ----------------
#define STG3_B  (4u * TILE_B)
#define NSTG3 3
#define MMA3_SMEM (NSTG3 * STG3_B)

__device__ __forceinline__ void load_chunk3(
    uint32_t stg, const bf16* __restrict__ Ahi, const bf16* __restrict__ Alo,
    const bf16* __restrict__ Bhi, const bf16* __restrict__ Blo,
    int m0, int n0, int kc, int tid)
{
    const int koff = kc * 32;
    #pragma unroll
    for (int j = 0; j < 8; j++) {
        int idx = tid + j * 256;
        int tile = idx >> 9;
        int rem = idx & 511;
        int r = rem >> 2, c = rem & 3;
        const bf16* src;
        int grow;
        if (tile == 0)      { src = Ahi; grow = m0 + r; }
        else if (tile == 1) { src = Alo; grow = m0 + r; }
        else if (tile == 2) { src = Bhi; grow = n0 + r; }
        else                { src = Blo; grow = n0 + r; }
        cpa16(sw_addr(stg + (uint32_t)tile * TILE_B, r, c),
              src + (size_t)grow * H_ + koff + c * 8);
    }
    CP_COMMIT();
}

__global__ void __launch_bounds__(256, 1) mma_gemm3(
    const bf16* __restrict__ Ahi, const bf16* __restrict__ Alo,
    const bf16* __restrict__ Bhi, const bf16* __restrict__ Blo,
    const float* __restrict__ bias1, const float* __restrict__ bias2,
    float* __restrict__ C, int ldn)
{
    extern __shared__ char smc[];
    const uint32_t smb = smem_u32(smc);
    const int tid = threadIdx.x;
    const int wid = tid >> 5, lid = tid & 31;
    const int wm = wid >> 2, wn = wid & 3;
    const int m0 = blockIdx.x * 128;
    const int n0 = blockIdx.y * 128;

    float acc[4][4][4];
    #pragma unroll
    for (int i = 0; i < 4; i++)
        #pragma unroll
        for (int j = 0; j < 4; j++)
            #pragma unroll
            for (int q = 0; q < 4; q++) acc[i][j][q] = 0.0f;

    const int l7 = lid & 7;
    const int lb8 = (lid >> 3) & 1;
    const int lb16 = lid >> 4;
    const int lm = lid >> 3;

    load_chunk3(smb,          Ahi, Alo, Bhi, Blo, m0, n0, 0, tid);
    load_chunk3(smb + STG3_B, Ahi, Alo, Bhi, Blo, m0, n0, 1, tid);

    for (int i = 0; i < NCC; i++) {
        if (i < NCC - 1) { CP_WAIT1(); } else { CP_WAIT0(); }
        __syncthreads();

        const uint32_t stg = smb + (uint32_t)(i % NSTG3) * STG3_B;
        const uint32_t tAhi = stg, tAlo = stg + TILE_B;
        const uint32_t tBhi = stg + 2 * TILE_B, tBlo = stg + 3 * TILE_B;

        #pragma unroll
        for (int ks = 0; ks < 2; ks++) {
            uint32_t ahi[4][4], alo[4][4], bhi[4][2], blo[4][2];
            const int ach = ks * 2 + lb16;
            #pragma unroll
            for (int mi = 0; mi < 4; mi++) {
                int row = wm * 64 + mi * 16 + l7 + lb8 * 8;
                ldsm4(ahi[mi][0], ahi[mi][1], ahi[mi][2], ahi[mi][3], sw_addr(tAhi, row, ach));
                ldsm4(alo[mi][0], alo[mi][1], alo[mi][2], alo[mi][3], sw_addr(tAlo, row, ach));
            }
            const int bch = ks * 2 + (lm & 1);
            #pragma unroll
            for (int p = 0; p < 2; p++) {
                int row = wn * 32 + p * 16 + l7 + ((lm >= 2) ? 8 : 0);
                uint32_t r0, r1, r2, r3;
                ldsm4(r0, r1, r2, r3, sw_addr(tBhi, row, bch));
                bhi[2*p][0] = r0; bhi[2*p][1] = r1; bhi[2*p+1][0] = r2; bhi[2*p+1][1] = r3;
                ldsm4(r0, r1, r2, r3, sw_addr(tBlo, row, bch));
                blo[2*p][0] = r0; blo[2*p][1] = r1; blo[2*p+1][0] = r2; blo[2*p+1][1] = r3;
            }
            #pragma unroll
            for (int mi = 0; mi < 4; mi++)
                #pragma unroll
                for (int nj = 0; nj < 4; nj++) {
                    mma_bf(acc[mi][nj], ahi[mi], bhi[nj]);
                    mma_bf(acc[mi][nj], alo[mi], bhi[nj]);
                    mma_bf(acc[mi][nj], ahi[mi], blo[nj]);
                }
        }

        if (i + 2 < NCC)
            load_chunk3(smb + (uint32_t)((i + 2) % NSTG3) * STG3_B,
                        Ahi, Alo, Bhi, Blo, m0, n0, i + 2, tid);
    }

    const int gid = lid >> 2, tig = lid & 3;
    #pragma unroll
    for (int nj = 0; nj < 4; nj++) {
        const int col = n0 + wn * 32 + nj * 8 + tig * 2;
        float2 bv;
        bv.x = bias1[col]; bv.y = bias1[col + 1];
        if (bias2) { bv.x += bias2[col]; bv.y += bias2[col + 1]; }
        #pragma unroll
        for (int mi = 0; mi < 4; mi++) {
            const int r0 = m0 + wm * 64 + mi * 16 + gid;
            float2 v0 = {acc[mi][nj][0] + bv.x, acc[mi][nj][1] + bv.y};
            float2 v1 = {acc[mi][nj][2] + bv.x, acc[mi][nj][3] + bv.y};
            *(float2*)(C + (size_t)r0 * ldn + col) = v0;
            *(float2*)(C + (size_t)(r0 + 8) * ldn + col) = v1;
        }
    }
}

// ---------------- fp16 single-term output GEMM (2 CTAs/SM, 4 stages) ----------
#define STG1_B  (2u * TILE_B)      // Ah, Bh = 16 KB
#define NSTG1 4
#define MMA1_SMEM (NSTG1 * STG1_B) // 64 KB

__device__ __forceinline__ void load_chunk1(
    uint32_t stg, const half* __restrict__ Ah, const half* __restrict__ Bh,
    int m0, int n0, int kc, int tid)
{
    const int koff = kc * 32;
    #pragma unroll
    for (int j = 0; j < 4; j++) {
        int idx = tid + j * 256;
        int tile = idx >> 9;               // 0:Ah 1:Bh
        int rem = idx & 511;
        int r = rem >> 2, c = rem & 3;
        const half* src = tile ? Bh : Ah;
        int grow = (tile ? n0 : m0) + r;
        cpa16(sw_addr(stg + (uint32_t)tile * TILE_B, r, c),
              src + (size_t)grow * H_ + koff + c * 8);
    }
    CP_COMMIT();
}

__global__ void __launch_bounds__(256, 2) mma_gemm1(
    const half* __restrict__ Ah, const half* __restrict__ Bh,
    const float* __restrict__ bias1,
    float* __restrict__ C, int ldn, float* __restrict__ lastout)
{
    extern __shared__ char smc[];
    const uint32_t smb = smem_u32(smc);
    const int tid = threadIdx.x;
    const int wid = tid >> 5, lid = tid & 31;
    const int wm = wid >> 2, wn = wid & 3;
    const int m0 = blockIdx.x * 128;
    const int n0 = blockIdx.y * 128;

    float acc[4][4][4];
    #pragma unroll
    for (int i = 0; i < 4; i++)
        #pragma unroll
        for (int j = 0; j < 4; j++)
            #pragma unroll
            for (int q = 0; q < 4; q++) acc[i][j][q] = 0.0f;

    const int l7 = lid & 7;
    const int lb8 = (lid >> 3) & 1;
    const int lb16 = lid >> 4;
    const int lm = lid >> 3;

    // prologue: chunks 0..2 into stages 0..2
    load_chunk1(smb,              Ah, Bh, m0, n0, 0, tid);
    load_chunk1(smb + STG1_B,     Ah, Bh, m0, n0, 1, tid);
    load_chunk1(smb + 2 * STG1_B, Ah, Bh, m0, n0, 2, tid);

    for (int i = 0; i < NCC; i++) {
        if (i + 3 < NCC) {
            load_chunk1(smb + (uint32_t)((i + 3) % NSTG1) * STG1_B,
                        Ah, Bh, m0, n0, i + 3, tid);
            CP_WAIT3();
        } else if (i + 2 < NCC) { CP_WAIT2(); }
        else if (i + 1 < NCC)   { CP_WAIT1(); }
        else                    { CP_WAIT0(); }
        __syncthreads();

        const uint32_t stg = smb + (uint32_t)(i % NSTG1) * STG1_B;
        const uint32_t tAh = stg, tBh = stg + TILE_B;

        #pragma unroll
        for (int ks = 0; ks < 2; ks++) {
            uint32_t a[4][4], bh[4][2];
            const int ach = ks * 2 + lb16;
            const int bch = ks * 2 + (lm & 1);
            #pragma unroll
            for (int p = 0; p < 2; p++) {
                int row = wn * 32 + p * 16 + l7 + ((lm >= 2) ? 8 : 0);
                uint32_t r0, r1, r2, r3;
                ldsm4(r0, r1, r2, r3, sw_addr(tBh, row, bch));
                bh[2*p][0] = r0; bh[2*p][1] = r1; bh[2*p+1][0] = r2; bh[2*p+1][1] = r3;
            }
            #pragma unroll
            for (int mi = 0; mi < 4; mi++) {
                int row = wm * 64 + mi * 16 + l7 + lb8 * 8;
                ldsm4(a[mi][0], a[mi][1], a[mi][2], a[mi][3], sw_addr(tAh, row, ach));
            }
            #pragma unroll
            for (int mi = 0; mi < 4; mi++)
                #pragma unroll
                for (int nj = 0; nj < 4; nj++)
                    mma_fp(acc[mi][nj], a[mi], bh[nj]);
        }
        __syncthreads();
    }

    const int gid = lid >> 2, tig = lid & 3;
    #pragma unroll
    for (int nj = 0; nj < 4; nj++) {
        const int col = n0 + wn * 32 + nj * 8 + tig * 2;
        float2 bv;
        bv.x = bias1[col]; bv.y = bias1[col + 1];
        #pragma unroll
        for (int mi = 0; mi < 4; mi++) {
            const int r0 = m0 + wm * 64 + mi * 16 + gid;
            float2 v0 = {acc[mi][nj][0] + bv.x, acc[mi][nj][1] + bv.y};
            float2 v1 = {acc[mi][nj][2] + bv.x, acc[mi][nj][3] + bv.y};
            *(float2*)(C + (size_t)r0 * ldn + col) = v0;
            *(float2*)(C + (size_t)(r0 + 8) * ldn + col) = v1;
            if (lastout && ((r0 + 8) & 127) == 127)
                *(float2*)(lastout + (size_t)blockIdx.x * ldn + col) = v1;
        }
    }
}

// ============================================================================
// Recurrence v3: h = tanh(xw[:,t,:] + h @ Whh^T)
// Direct L2 reads of h (__ldcg; 8 lanes/warp share each request — smem staging
// gave zero reuse), W in smem, tight-spin grid barrier (no nanosleep).
// ============================================================================
#define NB 128
#define HPAD 1028

__device__ __forceinline__ void gridbar_fast() {
    __syncthreads();
    if (threadIdx.x == 0) {
        __threadfence();
        ull a = atomicAdd(&g_acnt, 1ULL) + 1ULL;
        ull tgt = (a + NB - 1) / NB;
        if (a == tgt * NB) {
            atomicExch(&g_gen, tgt);              // release
        } else {
            while (*((volatile ull*)&g_gen) < tgt) { }   // tight spin (L2 poll)
        }
        __threadfence();
    }
    __syncthreads();
}

__global__ void __launch_bounds__(256, 1) rnn_rec3(
    const float* __restrict__ xw, const float* __restrict__ Whh,
    const float* __restrict__ hinit, float* __restrict__ y, float* __restrict__ hfin)
{
    __shared__ float w_s[8 * HPAD];            // block's 8 W rows
    __shared__ float hv_s[8 * 33];

    const int tid = threadIdx.x;
    const int blk = blockIdx.x;
    const int wrp = tid >> 5, lane = tid & 31;
    const int i_loc = lane >> 2;
    const int b = wrp * 4 + (lane & 3);
    const int i = blk * 8 + i_loc;

    // stage W rows for this block (once): 8 rows x 1024 floats = 2048 float4
    #pragma unroll
    for (int q = 0; q < 8; q++) {
        int fi = tid + q * 256;
        int r = fi >> 8, c = (fi & 255) * 4;
        *(float4*)&w_s[r * HPAD + c] =
            *(const float4*)&Whh[(size_t)(blk * 8 + r) * H_ + c];
    }
    g_hbuf[0][blk * 256 + tid] = hinit[blk * 256 + tid];
    gridbar_fast();

    const float* wrow = w_s + i_loc * HPAD;

    for (int t = 0; t < T_; t++) {
        const float* hrow = g_hbuf[t & 1] + (size_t)b * H_;
        float xv = xw[((size_t)b * T_ + t) * H_ + i];

        ull a0 = 0, a1 = 0;
        #pragma unroll 8
        for (int j = 0; j < 1024; j += 8) {
            ulonglong2 hq0 = __ldcg((const ulonglong2*)(hrow + j));
            ulonglong2 hq1 = __ldcg((const ulonglong2*)(hrow + j + 4));
            ulonglong2 wq0 = *(const ulonglong2*)(wrow + j);
            ulonglong2 wq1 = *(const ulonglong2*)(wrow + j + 4);
            ffma2(a0, hq0.x, wq0.x);
            ffma2(a1, hq0.y, wq0.y);
            ffma2(a0, hq1.x, wq1.x);
            ffma2(a1, hq1.y, wq1.y);
        }
        float2 f0 = unpack2(a0), f1 = unpack2(a1);
        float dot = (f0.x + f0.y) + (f1.x + f1.y);
        float hv = tanhf(dot + xv);

        hv_s[i_loc * 33 + b] = hv;
        __syncthreads();

        {
            int bb = tid >> 3, io = tid & 7;
            float v = hv_s[io * 33 + bb];
            g_hbuf[(t + 1) & 1][bb * H_ + blk * 8 + io] = v;
            y[((size_t)bb * T_ + t) * H_ + blk * 8 + io] = v;
            if (t == T_ - 1) hfin[bb * H_ + blk * 8 + io] = v;
        }
        gridbar_fast();
    }
}

// ============================================================================
extern "C" void kernel_launch(void* const* d_in, const int* in_sizes, int n_in,
                              void* d_out, int out_size)
{
    const int*   tok  = (const int*)  d_in[0];
    const float* hid  = (const float*)d_in[1];
    const float* emb  = (const float*)d_in[2];
    const float* Wih0 = (const float*)d_in[3];
    const float* Whh0 = (const float*)d_in[4];
    const float* bih0 = (const float*)d_in[5];
    const float* bhh0 = (const float*)d_in[6];
    const float* Wih1 = (const float*)d_in[7];
    const float* Whh1 = (const float*)d_in[8];
    const float* bih1 = (const float*)d_in[9];
    const float* bhh1 = (const float*)d_in[10];
    const float* Wout = (const float*)d_in[11];
    const float* bout = (const float*)d_in[12];
    float* out = (float*)d_out;

    float *bufA, *bufB;
    bf16 *Ahi, *Alo, *Phi, *Plo;
    half *Wh16, *Ah16;
    cudaGetSymbolAddress((void**)&bufA, g_bufA);
    cudaGetSymbolAddress((void**)&bufB, g_bufB);
    cudaGetSymbolAddress((void**)&Ahi, g_Ahi);
    cudaGetSymbolAddress((void**)&Alo, g_Alo);
    cudaGetSymbolAddress((void**)&Phi, g_Phi);
    cudaGetSymbolAddress((void**)&Plo, g_Plo);
    cudaGetSymbolAddress((void**)&Wh16, g_Wh16);
    cudaGetSymbolAddress((void**)&Ah16, g_Ah16);

    cudaFuncSetAttribute(mma_gemm3, cudaFuncAttributeMaxDynamicSharedMemorySize, MMA3_SMEM);
    cudaFuncSetAttribute(mma_gemm1, cudaFuncAttributeMaxDynamicSharedMemorySize, MMA1_SMEM);

    // W_out -> fp16
    conv_f16<<<(int)((size_t)V_ * H_ / 2048), 256>>>(Wout, Wh16);

    // layer 0
    split_gather_bf<<<M_, 256>>>(emb, tok, Ahi, Alo);
    split_bf<<<(int)((size_t)H_ * H_ / 1024), 256>>>(Wih0, Phi, Plo);
    mma_gemm3<<<dim3(M_ / 128, H_ / 128), 256, MMA3_SMEM>>>(
        Ahi, Alo, Phi, Plo, bih0, bhh0, bufA, H_);
    rnn_rec3<<<NB, 256>>>(bufA, Whh0, hid, bufB, out + OUT_HID);

    // layer 1
    split_bf<<<(int)((size_t)M_ * H_ / 1024), 256>>>(bufB, Ahi, Alo);
    split_bf<<<(int)((size_t)H_ * H_ / 1024), 256>>>(Wih1, Phi, Plo);
    mma_gemm3<<<dim3(M_ / 128, H_ / 128), 256, MMA3_SMEM>>>(
        Ahi, Alo, Phi, Plo, bih1, bhh1, bufA, H_);
    rnn_rec3<<<NB, 256>>>(bufA, Whh1, hid + B_ * H_, bufB,
                          out + OUT_HID + (size_t)B_ * H_);

    // output projection: fp16 single-term, last_output fused
    conv_f16<<<(int)((size_t)M_ * H_ / 2048), 256>>>(bufB, Ah16);
    mma_gemm1<<<dim3(M_ / 128, V_ / 128), 256, MMA1_SMEM>>>(
        Ah16, Wh16, bout, out, V_, out + OUT_LAST);
}

// round 15
// speedup vs baseline: 1.9654x; 1.9654x over previous
#include <cuda_runtime.h>
#include <cuda_bf16.h>
#include <cuda_fp16.h>
#include <cstdint>

// Problem dims
#define V_ 32000
#define E_ 1024
#define H_ 1024
#define B_ 32
#define T_ 128
#define M_ (B_ * T_)          // 4096

// Output layout in d_out
#define OUT_HID  ((size_t)M_ * V_)
#define OUT_LAST (OUT_HID + 2ULL * B_ * H_)

typedef unsigned long long ull;
typedef __nv_bfloat16 bf16;

// ---------------- scratch (device globals) ----------------
__device__ float g_bufA[M_ * H_];
__device__ float g_bufB[M_ * H_];
__device__ float g_hbuf[2][B_ * H_];
__device__ ull   g_acnt = 0;
__device__ ull   g_gen  = 0;

__device__ bf16 g_Ahi[(size_t)M_ * H_];      // proj A splits (bf16)
__device__ bf16 g_Alo[(size_t)M_ * H_];
__device__ bf16 g_Phi[(size_t)H_ * H_];      // proj W splits (bf16)
__device__ bf16 g_Plo[(size_t)H_ * H_];
__device__ half g_Wh16[(size_t)V_ * H_];     // W_out fp16
__device__ half g_Ah16[(size_t)M_ * H_];     // output-A fp16

// ---------------- helpers ----------------
__device__ __forceinline__ void ffma2(ull& c, ull a, ull b) {
    asm("fma.rn.f32x2 %0, %1, %2, %0;" : "+l"(c) : "l"(a), "l"(b));
}
__device__ __forceinline__ float2 unpack2(ull v) {
    float2 r; asm("mov.b64 {%0, %1}, %2;" : "=f"(r.x), "=f"(r.y) : "l"(v)); return r;
}
__device__ __forceinline__ uint32_t smem_u32(const void* p) {
    uint32_t a;
    asm("{ .reg .u64 t; cvta.to.shared.u64 t, %1; cvt.u32.u64 %0, t; }" : "=r"(a) : "l"(p));
    return a;
}
__device__ __forceinline__ void cpa16(uint32_t d, const void* s) {
    asm volatile("cp.async.cg.shared.global [%0], [%1], 16;" :: "r"(d), "l"(s));
}
#define CP_COMMIT() asm volatile("cp.async.commit_group;" ::: "memory")
#define CP_WAIT0()  asm volatile("cp.async.wait_group 0;" ::: "memory")
#define CP_WAIT1()  asm volatile("cp.async.wait_group 1;" ::: "memory")
#define CP_WAIT2()  asm volatile("cp.async.wait_group 2;" ::: "memory")
#define CP_WAIT3()  asm volatile("cp.async.wait_group 3;" ::: "memory")

__device__ __forceinline__ void ldsm4(uint32_t& r0, uint32_t& r1, uint32_t& r2, uint32_t& r3,
                                      uint32_t addr) {
    asm volatile("ldmatrix.sync.aligned.m8n8.x4.shared.b16 {%0,%1,%2,%3}, [%4];"
                 : "=r"(r0), "=r"(r1), "=r"(r2), "=r"(r3) : "r"(addr));
}
__device__ __forceinline__ void mma_bf(float* c, const uint32_t* a, const uint32_t* b) {
    asm volatile(
        "mma.sync.aligned.m16n8k16.row.col.f32.bf16.bf16.f32 "
        "{%0,%1,%2,%3}, {%4,%5,%6,%7}, {%8,%9}, {%0,%1,%2,%3};"
        : "+f"(c[0]), "+f"(c[1]), "+f"(c[2]), "+f"(c[3])
        : "r"(a[0]), "r"(a[1]), "r"(a[2]), "r"(a[3]), "r"(b[0]), "r"(b[1]));
}
__device__ __forceinline__ void mma_fp(float* c, const uint32_t* a, const uint32_t* b) {
    asm volatile(
        "mma.sync.aligned.m16n8k16.row.col.f32.f16.f16.f32 "
        "{%0,%1,%2,%3}, {%4,%5,%6,%7}, {%8,%9}, {%0,%1,%2,%3};"
        : "+f"(c[0]), "+f"(c[1]), "+f"(c[2]), "+f"(c[3])
        : "r"(a[0]), "r"(a[1]), "r"(a[2]), "r"(a[3]), "r"(b[0]), "r"(b[1]));
}

// ============================================================================
// Conversion kernels
// ============================================================================
__global__ void split_bf(const float* __restrict__ src,
                         bf16* __restrict__ hi, bf16* __restrict__ lo)
{
    size_t i = ((size_t)blockIdx.x * 256 + threadIdx.x) * 4;
    float4 v = *(const float4*)(src + i);
    union { bf16 h[4]; uint2 u; } H, L;
    float vv[4] = {v.x, v.y, v.z, v.w};
    #pragma unroll
    for (int j = 0; j < 4; j++) {
        bf16 h = __float2bfloat16_rn(vv[j]);
        H.h[j] = h;
        L.h[j] = __float2bfloat16_rn(vv[j] - __bfloat162float(h));
    }
    *(uint2*)(hi + i) = H.u;
    *(uint2*)(lo + i) = L.u;
}

__global__ void split_gather_bf(const float* __restrict__ emb, const int* __restrict__ tok,
                                bf16* __restrict__ hi, bf16* __restrict__ lo)
{
    int m = blockIdx.x;
    int row = tok[m];
    size_t s = (size_t)row * H_ + threadIdx.x * 4;
    size_t d = (size_t)m * H_ + threadIdx.x * 4;
    float4 v = *(const float4*)(emb + s);
    union { bf16 h[4]; uint2 u; } H, L;
    float vv[4] = {v.x, v.y, v.z, v.w};
    #pragma unroll
    for (int j = 0; j < 4; j++) {
        bf16 h = __float2bfloat16_rn(vv[j]);
        H.h[j] = h;
        L.h[j] = __float2bfloat16_rn(vv[j] - __bfloat162float(h));
    }
    *(uint2*)(hi + d) = H.u;
    *(uint2*)(lo + d) = L.u;
}

__global__ void conv_f16(const float* __restrict__ src, half* __restrict__ dst)
{
    size_t i = ((size_t)blockIdx.x * 256 + threadIdx.x) * 8;
    float4 v0 = *(const float4*)(src + i);
    float4 v1 = *(const float4*)(src + i + 4);
    union { half h[8]; uint4 u; } O;
    O.h[0] = __float2half_rn(v0.x); O.h[1] = __float2half_rn(v0.y);
    O.h[2] = __float2half_rn(v0.z); O.h[3] = __float2half_rn(v0.w);
    O.h[4] = __float2half_rn(v1.x); O.h[5] = __float2half_rn(v1.y);
    O.h[6] = __float2half_rn(v1.z); O.h[7] = __float2half_rn(v1.w);
    *(uint4*)(dst + i) = O.u;
}

// ============================================================================
// Shared GEMM pieces: 128x128 tile, K-chunk 32, row = 64 B of 16-bit elems
// ============================================================================
__device__ __forceinline__ uint32_t sw_addr(uint32_t tile, int row, int chunk) {
    return tile + (uint32_t)row * 64u + (uint32_t)((chunk ^ ((row >> 1) & 3)) * 16);
}
#define TILE_B 8192u
#define NCC 32

// ---------------- bf16 3-term projection GEMM (1 CTA/SM) ----------------
#define STG3_B  (4u * TILE_B)
#define NSTG3 3
#define MMA3_SMEM (NSTG3 * STG3_B)

__device__ __forceinline__ void load_chunk3(
    uint32_t stg, const bf16* __restrict__ Ahi, const bf16* __restrict__ Alo,
    const bf16* __restrict__ Bhi, const bf16* __restrict__ Blo,
    int m0, int n0, int kc, int tid)
{
    const int koff = kc * 32;
    #pragma unroll
    for (int j = 0; j < 8; j++) {
        int idx = tid + j * 256;
        int tile = idx >> 9;
        int rem = idx & 511;
        int r = rem >> 2, c = rem & 3;
        const bf16* src;
        int grow;
        if (tile == 0)      { src = Ahi; grow = m0 + r; }
        else if (tile == 1) { src = Alo; grow = m0 + r; }
        else if (tile == 2) { src = Bhi; grow = n0 + r; }
        else                { src = Blo; grow = n0 + r; }
        cpa16(sw_addr(stg + (uint32_t)tile * TILE_B, r, c),
              src + (size_t)grow * H_ + koff + c * 8);
    }
    CP_COMMIT();
}

__global__ void __launch_bounds__(256, 1) mma_gemm3(
    const bf16* __restrict__ Ahi, const bf16* __restrict__ Alo,
    const bf16* __restrict__ Bhi, const bf16* __restrict__ Blo,
    const float* __restrict__ bias1, const float* __restrict__ bias2,
    float* __restrict__ C, int ldn)
{
    extern __shared__ char smc[];
    const uint32_t smb = smem_u32(smc);
    const int tid = threadIdx.x;
    const int wid = tid >> 5, lid = tid & 31;
    const int wm = wid >> 2, wn = wid & 3;
    const int m0 = blockIdx.x * 128;
    const int n0 = blockIdx.y * 128;

    float acc[4][4][4];
    #pragma unroll
    for (int i = 0; i < 4; i++)
        #pragma unroll
        for (int j = 0; j < 4; j++)
            #pragma unroll
            for (int q = 0; q < 4; q++) acc[i][j][q] = 0.0f;

    const int l7 = lid & 7;
    const int lb8 = (lid >> 3) & 1;
    const int lb16 = lid >> 4;
    const int lm = lid >> 3;

    load_chunk3(smb,          Ahi, Alo, Bhi, Blo, m0, n0, 0, tid);
    load_chunk3(smb + STG3_B, Ahi, Alo, Bhi, Blo, m0, n0, 1, tid);

    for (int i = 0; i < NCC; i++) {
        if (i < NCC - 1) { CP_WAIT1(); } else { CP_WAIT0(); }
        __syncthreads();

        const uint32_t stg = smb + (uint32_t)(i % NSTG3) * STG3_B;
        const uint32_t tAhi = stg, tAlo = stg + TILE_B;
        const uint32_t tBhi = stg + 2 * TILE_B, tBlo = stg + 3 * TILE_B;

        #pragma unroll
        for (int ks = 0; ks < 2; ks++) {
            uint32_t ahi[4][4], alo[4][4], bhi[4][2], blo[4][2];
            const int ach = ks * 2 + lb16;
            #pragma unroll
            for (int mi = 0; mi < 4; mi++) {
                int row = wm * 64 + mi * 16 + l7 + lb8 * 8;
                ldsm4(ahi[mi][0], ahi[mi][1], ahi[mi][2], ahi[mi][3], sw_addr(tAhi, row, ach));
                ldsm4(alo[mi][0], alo[mi][1], alo[mi][2], alo[mi][3], sw_addr(tAlo, row, ach));
            }
            const int bch = ks * 2 + (lm & 1);
            #pragma unroll
            for (int p = 0; p < 2; p++) {
                int row = wn * 32 + p * 16 + l7 + ((lm >= 2) ? 8 : 0);
                uint32_t r0, r1, r2, r3;
                ldsm4(r0, r1, r2, r3, sw_addr(tBhi, row, bch));
                bhi[2*p][0] = r0; bhi[2*p][1] = r1; bhi[2*p+1][0] = r2; bhi[2*p+1][1] = r3;
                ldsm4(r0, r1, r2, r3, sw_addr(tBlo, row, bch));
                blo[2*p][0] = r0; blo[2*p][1] = r1; blo[2*p+1][0] = r2; blo[2*p+1][1] = r3;
            }
            #pragma unroll
            for (int mi = 0; mi < 4; mi++)
                #pragma unroll
                for (int nj = 0; nj < 4; nj++) {
                    mma_bf(acc[mi][nj], ahi[mi], bhi[nj]);
                    mma_bf(acc[mi][nj], alo[mi], bhi[nj]);
                    mma_bf(acc[mi][nj], ahi[mi], blo[nj]);
                }
        }

        if (i + 2 < NCC)
            load_chunk3(smb + (uint32_t)((i + 2) % NSTG3) * STG3_B,
                        Ahi, Alo, Bhi, Blo, m0, n0, i + 2, tid);
    }

    const int gid = lid >> 2, tig = lid & 3;
    #pragma unroll
    for (int nj = 0; nj < 4; nj++) {
        const int col = n0 + wn * 32 + nj * 8 + tig * 2;
        float2 bv;
        bv.x = bias1[col]; bv.y = bias1[col + 1];
        if (bias2) { bv.x += bias2[col]; bv.y += bias2[col + 1]; }
        #pragma unroll
        for (int mi = 0; mi < 4; mi++) {
            const int r0 = m0 + wm * 64 + mi * 16 + gid;
            float2 v0 = {acc[mi][nj][0] + bv.x, acc[mi][nj][1] + bv.y};
            float2 v1 = {acc[mi][nj][2] + bv.x, acc[mi][nj][3] + bv.y};
            *(float2*)(C + (size_t)r0 * ldn + col) = v0;
            *(float2*)(C + (size_t)(r0 + 8) * ldn + col) = v1;
        }
    }
}

// ---------------- fp16 single-term output GEMM (2 CTAs/SM, 4 stages) ----------
#define STG1_B  (2u * TILE_B)      // Ah, Bh = 16 KB
#define NSTG1 4
#define MMA1_SMEM (NSTG1 * STG1_B) // 64 KB

__device__ __forceinline__ void load_chunk1(
    uint32_t stg, const half* __restrict__ Ah, const half* __restrict__ Bh,
    int m0, int n0, int kc, int tid)
{
    const int koff = kc * 32;
    #pragma unroll
    for (int j = 0; j < 4; j++) {
        int idx = tid + j * 256;
        int tile = idx >> 9;               // 0:Ah 1:Bh
        int rem = idx & 511;
        int r = rem >> 2, c = rem & 3;
        const half* src = tile ? Bh : Ah;
        int grow = (tile ? n0 : m0) + r;
        cpa16(sw_addr(stg + (uint32_t)tile * TILE_B, r, c),
              src + (size_t)grow * H_ + koff + c * 8);
    }
    CP_COMMIT();
}

__global__ void __launch_bounds__(256, 2) mma_gemm1(
    const half* __restrict__ Ah, const half* __restrict__ Bh,
    const float* __restrict__ bias1,
    float* __restrict__ C, int ldn, float* __restrict__ lastout)
{
    extern __shared__ char smc[];
    const uint32_t smb = smem_u32(smc);
    const int tid = threadIdx.x;
    const int wid = tid >> 5, lid = tid & 31;
    const int wm = wid >> 2, wn = wid & 3;
    const int m0 = blockIdx.x * 128;
    const int n0 = blockIdx.y * 128;

    float acc[4][4][4];
    #pragma unroll
    for (int i = 0; i < 4; i++)
        #pragma unroll
        for (int j = 0; j < 4; j++)
            #pragma unroll
            for (int q = 0; q < 4; q++) acc[i][j][q] = 0.0f;

    const int l7 = lid & 7;
    const int lb8 = (lid >> 3) & 1;
    const int lb16 = lid >> 4;
    const int lm = lid >> 3;

    // prologue: chunks 0..2 into stages 0..2
    load_chunk1(smb,              Ah, Bh, m0, n0, 0, tid);
    load_chunk1(smb + STG1_B,     Ah, Bh, m0, n0, 1, tid);
    load_chunk1(smb + 2 * STG1_B, Ah, Bh, m0, n0, 2, tid);

    for (int i = 0; i < NCC; i++) {
        if (i + 3 < NCC) {
            load_chunk1(smb + (uint32_t)((i + 3) % NSTG1) * STG1_B,
                        Ah, Bh, m0, n0, i + 3, tid);
            CP_WAIT3();
        } else if (i + 2 < NCC) { CP_WAIT2(); }
        else if (i + 1 < NCC)   { CP_WAIT1(); }
        else                    { CP_WAIT0(); }
        __syncthreads();

        const uint32_t stg = smb + (uint32_t)(i % NSTG1) * STG1_B;
        const uint32_t tAh = stg, tBh = stg + TILE_B;

        #pragma unroll
        for (int ks = 0; ks < 2; ks++) {
            uint32_t a[4][4], bh[4][2];
            const int ach = ks * 2 + lb16;
            const int bch = ks * 2 + (lm & 1);
            #pragma unroll
            for (int p = 0; p < 2; p++) {
                int row = wn * 32 + p * 16 + l7 + ((lm >= 2) ? 8 : 0);
                uint32_t r0, r1, r2, r3;
                ldsm4(r0, r1, r2, r3, sw_addr(tBh, row, bch));
                bh[2*p][0] = r0; bh[2*p][1] = r1; bh[2*p+1][0] = r2; bh[2*p+1][1] = r3;
            }
            #pragma unroll
            for (int mi = 0; mi < 4; mi++) {
                int row = wm * 64 + mi * 16 + l7 + lb8 * 8;
                ldsm4(a[mi][0], a[mi][1], a[mi][2], a[mi][3], sw_addr(tAh, row, ach));
            }
            #pragma unroll
            for (int mi = 0; mi < 4; mi++)
                #pragma unroll
                for (int nj = 0; nj < 4; nj++)
                    mma_fp(acc[mi][nj], a[mi], bh[nj]);
        }
        __syncthreads();
    }

    const int gid = lid >> 2, tig = lid & 3;
    #pragma unroll
    for (int nj = 0; nj < 4; nj++) {
        const int col = n0 + wn * 32 + nj * 8 + tig * 2;
        float2 bv;
        bv.x = bias1[col]; bv.y = bias1[col + 1];
        #pragma unroll
        for (int mi = 0; mi < 4; mi++) {
            const int r0 = m0 + wm * 64 + mi * 16 + gid;
            float2 v0 = {acc[mi][nj][0] + bv.x, acc[mi][nj][1] + bv.y};
            float2 v1 = {acc[mi][nj][2] + bv.x, acc[mi][nj][3] + bv.y};
            *(float2*)(C + (size_t)r0 * ldn + col) = v0;
            *(float2*)(C + (size_t)(r0 + 8) * ldn + col) = v1;
            if (lastout && ((r0 + 8) & 127) == 127)
                *(float2*)(lastout + (size_t)blockIdx.x * ldn + col) = v1;
        }
    }
}

// ============================================================================
// Recurrence v2b: h = tanh(xw[:,t,:] + h @ Whh^T)
// Identical to the R11-passing rec2 (cp.async staging) EXCEPT the step barrier:
// arrivals use red.global.add (no-return, pipelined at L2) and completion is a
// poll of the monotonic counter against base + step*NB. The init barrier keeps
// the R11 atomicAdd scheme (also recovers `base` = counter value at init done).
// ============================================================================
#define NB 128
#define HPAD 1028
#define REC_SMEM ((32 * HPAD + 8 * HPAD + 8 * 33 + 4) * 4)

__global__ void __launch_bounds__(256, 1) rnn_rec2(
    const float* __restrict__ xw, const float* __restrict__ Whh,
    const float* __restrict__ hinit, float* __restrict__ y, float* __restrict__ hfin)
{
    extern __shared__ float smf[];
    float* h_s  = smf;                         // [32][HPAD]
    float* w_s  = smf + 32 * HPAD;             // [8][HPAD]
    float* hv_s = smf + 40 * HPAD;             // [8][33]

    const int tid = threadIdx.x;
    const int blk = blockIdx.x;
    const int wrp = tid >> 5, lane = tid & 31;
    const int i_loc = lane >> 2;
    const int b = wrp * 4 + (lane & 3);
    const int i = blk * 8 + i_loc;

    // stage W rows for this block (once): 8 rows x 1024 floats = 2048 float4
    #pragma unroll
    for (int q = 0; q < 8; q++) {
        int fi = tid + q * 256;
        int r = fi >> 8, c = (fi & 255) * 4;
        *(float4*)&w_s[r * HPAD + c] =
            *(const float4*)&Whh[(size_t)(blk * 8 + r) * H_ + c];
    }
    g_hbuf[0][blk * 256 + tid] = hinit[blk * 256 + tid];

    // ---- init barrier (R11 scheme) + recover counter base ----
    ull base = 0;
    __syncthreads();
    if (tid == 0) {
        __threadfence();
        ull a = atomicAdd(&g_acnt, 1ULL) + 1ULL;
        ull tgt = (a + NB - 1) / NB;           // generation number
        if (a == tgt * NB) {
            atomicExch(&g_gen, tgt);
        } else {
            while (*((volatile ull*)&g_gen) < tgt) { __nanosleep(64); }
        }
        __threadfence();
        base = tgt * NB;                       // counter value at init completion
    }
    __syncthreads();

    const uint32_t h_sb = smem_u32(h_s);
    const float* wrow = w_s + i_loc * HPAD;
    const float* hrow = h_s + b * HPAD;

    for (int t = 0; t < T_; t++) {
        const float* hcur = g_hbuf[t & 1];
        // half A: j in [0,512): 32 rows x 128 chunks of 16B
        #pragma unroll
        for (int q = 0; q < 16; q++) {
            int ci = tid + q * 256;
            int r = ci >> 7, c = ci & 127;
            cpa16(h_sb + (uint32_t)(r * HPAD * 4 + c * 16), hcur + r * H_ + c * 4);
        }
        CP_COMMIT();
        // half B: j in [512,1024)
        #pragma unroll
        for (int q = 0; q < 16; q++) {
            int ci = tid + q * 256;
            int r = ci >> 7, c = 128 + (ci & 127);
            cpa16(h_sb + (uint32_t)(r * HPAD * 4 + c * 16), hcur + r * H_ + c * 4);
        }
        CP_COMMIT();

        float xv = xw[((size_t)b * T_ + t) * H_ + i];

        ull a0 = 0, a1 = 0;
        CP_WAIT1();
        __syncthreads();
        #pragma unroll 8
        for (int j = 0; j < 512; j += 4) {
            ulonglong2 hq = *(const ulonglong2*)(hrow + j);
            ulonglong2 wq = *(const ulonglong2*)(wrow + j);
            ffma2(a0, hq.x, wq.x);
            ffma2(a1, hq.y, wq.y);
        }
        CP_WAIT0();
        __syncthreads();
        #pragma unroll 8
        for (int j = 512; j < 1024; j += 4) {
            ulonglong2 hq = *(const ulonglong2*)(hrow + j);
            ulonglong2 wq = *(const ulonglong2*)(wrow + j);
            ffma2(a0, hq.x, wq.x);
            ffma2(a1, hq.y, wq.y);
        }
        float2 f0 = unpack2(a0), f1 = unpack2(a1);
        float dot = (f0.x + f0.y) + (f1.x + f1.y);
        float hv = tanhf(dot + xv);

        hv_s[i_loc * 33 + b] = hv;
        __syncthreads();

        {
            int bb = tid >> 3, io = tid & 7;
            float v = hv_s[io * 33 + bb];
            g_hbuf[(t + 1) & 1][bb * H_ + blk * 8 + io] = v;
            y[((size_t)bb * T_ + t) * H_ + blk * 8 + io] = v;
            if (t == T_ - 1) hfin[bb * H_ + blk * 8 + io] = v;
        }

        // ---- step barrier: red-based arrivals + monotonic counter poll ----
        __syncthreads();
        if (tid == 0) {
            __threadfence();
            asm volatile("red.global.add.u64 [%0], %1;"
                         :: "l"(&g_acnt), "l"(1ULL) : "memory");
            ull target = base + (ull)(t + 1) * NB;
            while (__ldcg(&g_acnt) < target) { __nanosleep(32); }
            __threadfence();
        }
        __syncthreads();
    }
}

// ============================================================================
extern "C" void kernel_launch(void* const* d_in, const int* in_sizes, int n_in,
                              void* d_out, int out_size)
{
    const int*   tok  = (const int*)  d_in[0];
    const float* hid  = (const float*)d_in[1];
    const float* emb  = (const float*)d_in[2];
    const float* Wih0 = (const float*)d_in[3];
    const float* Whh0 = (const float*)d_in[4];
    const float* bih0 = (const float*)d_in[5];
    const float* bhh0 = (const float*)d_in[6];
    const float* Wih1 = (const float*)d_in[7];
    const float* Whh1 = (const float*)d_in[8];
    const float* bih1 = (const float*)d_in[9];
    const float* bhh1 = (const float*)d_in[10];
    const float* Wout = (const float*)d_in[11];
    const float* bout = (const float*)d_in[12];
    float* out = (float*)d_out;

    float *bufA, *bufB;
    bf16 *Ahi, *Alo, *Phi, *Plo;
    half *Wh16, *Ah16;
    cudaGetSymbolAddress((void**)&bufA, g_bufA);
    cudaGetSymbolAddress((void**)&bufB, g_bufB);
    cudaGetSymbolAddress((void**)&Ahi, g_Ahi);
    cudaGetSymbolAddress((void**)&Alo, g_Alo);
    cudaGetSymbolAddress((void**)&Phi, g_Phi);
    cudaGetSymbolAddress((void**)&Plo, g_Plo);
    cudaGetSymbolAddress((void**)&Wh16, g_Wh16);
    cudaGetSymbolAddress((void**)&Ah16, g_Ah16);

    cudaFuncSetAttribute(mma_gemm3, cudaFuncAttributeMaxDynamicSharedMemorySize, MMA3_SMEM);
    cudaFuncSetAttribute(mma_gemm1, cudaFuncAttributeMaxDynamicSharedMemorySize, MMA1_SMEM);
    cudaFuncSetAttribute(rnn_rec2, cudaFuncAttributeMaxDynamicSharedMemorySize, REC_SMEM);

    // W_out -> fp16
    conv_f16<<<(int)((size_t)V_ * H_ / 2048), 256>>>(Wout, Wh16);

    // layer 0
    split_gather_bf<<<M_, 256>>>(emb, tok, Ahi, Alo);
    split_bf<<<(int)((size_t)H_ * H_ / 1024), 256>>>(Wih0, Phi, Plo);
    mma_gemm3<<<dim3(M_ / 128, H_ / 128), 256, MMA3_SMEM>>>(
        Ahi, Alo, Phi, Plo, bih0, bhh0, bufA, H_);
    rnn_rec2<<<NB, 256, REC_SMEM>>>(bufA, Whh0, hid, bufB, out + OUT_HID);

    // layer 1
    split_bf<<<(int)((size_t)M_ * H_ / 1024), 256>>>(bufB, Ahi, Alo);
    split_bf<<<(int)((size_t)H_ * H_ / 1024), 256>>>(Wih1, Phi, Plo);
    mma_gemm3<<<dim3(M_ / 128, H_ / 128), 256, MMA3_SMEM>>>(
        Ahi, Alo, Phi, Plo, bih1, bhh1, bufA, H_);
    rnn_rec2<<<NB, 256, REC_SMEM>>>(bufA, Whh1, hid + B_ * H_, bufB,
                                    out + OUT_HID + (size_t)B_ * H_);

    // output projection: fp16 single-term, last_output fused
    conv_f16<<<(int)((size_t)M_ * H_ / 2048), 256>>>(bufB, Ah16);
    mma_gemm1<<<dim3(M_ / 128, V_ / 128), 256, MMA1_SMEM>>>(
        Ah16, Wh16, bout, out, V_, out + OUT_LAST);
}

// round 17
// speedup vs baseline: 2.0392x; 1.0375x over previous
#include <cuda_runtime.h>
#include <cuda_bf16.h>
#include <cuda_fp16.h>
#include <cstdint>

// Problem dims
#define V_ 32000
#define E_ 1024
#define H_ 1024
#define B_ 32
#define T_ 128
#define M_ (B_ * T_)          // 4096

// Output layout in d_out
#define OUT_HID  ((size_t)M_ * V_)
#define OUT_LAST (OUT_HID + 2ULL * B_ * H_)

typedef unsigned long long ull;
typedef __nv_bfloat16 bf16;

// ---------------- scratch (device globals) ----------------
__device__ float g_bufA[M_ * H_];
__device__ float g_bufB[M_ * H_];
__device__ float g_h0buf[2][B_ * H_];
__device__ float g_h1buf[2][B_ * H_];
__device__ ull   g_acnt = 0;
__device__ ull   g_gen  = 0;

__device__ bf16 g_Ahi[(size_t)M_ * H_];      // proj A splits (bf16)
__device__ bf16 g_Alo[(size_t)M_ * H_];
__device__ bf16 g_Phi[(size_t)H_ * H_];      // proj W splits (bf16)
__device__ bf16 g_Plo[(size_t)H_ * H_];
__device__ half g_Wh16[(size_t)V_ * H_];     // W_out fp16
__device__ half g_Ah16[(size_t)M_ * H_];     // output-A fp16

// ---------------- helpers ----------------
__device__ __forceinline__ void ffma2(ull& c, ull a, ull b) {
    asm("fma.rn.f32x2 %0, %1, %2, %0;" : "+l"(c) : "l"(a), "l"(b));
}
__device__ __forceinline__ float2 unpack2(ull v) {
    float2 r; asm("mov.b64 {%0, %1}, %2;" : "=f"(r.x), "=f"(r.y) : "l"(v)); return r;
}
__device__ __forceinline__ uint32_t smem_u32(const void* p) {
    uint32_t a;
    asm("{ .reg .u64 t; cvta.to.shared.u64 t, %1; cvt.u32.u64 %0, t; }" : "=r"(a) : "l"(p));
    return a;
}
__device__ __forceinline__ void cpa16(uint32_t d, const void* s) {
    asm volatile("cp.async.cg.shared.global [%0], [%1], 16;" :: "r"(d), "l"(s));
}
#define CP_COMMIT() asm volatile("cp.async.commit_group;" ::: "memory")
#define CP_WAIT0()  asm volatile("cp.async.wait_group 0;" ::: "memory")
#define CP_WAIT1()  asm volatile("cp.async.wait_group 1;" ::: "memory")
#define CP_WAIT2()  asm volatile("cp.async.wait_group 2;" ::: "memory")
#define CP_WAIT3()  asm volatile("cp.async.wait_group 3;" ::: "memory")

__device__ __forceinline__ void ldsm4(uint32_t& r0, uint32_t& r1, uint32_t& r2, uint32_t& r3,
                                      uint32_t addr) {
    asm volatile("ldmatrix.sync.aligned.m8n8.x4.shared.b16 {%0,%1,%2,%3}, [%4];"
                 : "=r"(r0), "=r"(r1), "=r"(r2), "=r"(r3) : "r"(addr));
}
__device__ __forceinline__ void mma_bf(float* c, const uint32_t* a, const uint32_t* b) {
    asm volatile(
        "mma.sync.aligned.m16n8k16.row.col.f32.bf16.bf16.f32 "
        "{%0,%1,%2,%3}, {%4,%5,%6,%7}, {%8,%9}, {%0,%1,%2,%3};"
        : "+f"(c[0]), "+f"(c[1]), "+f"(c[2]), "+f"(c[3])
        : "r"(a[0]), "r"(a[1]), "r"(a[2]), "r"(a[3]), "r"(b[0]), "r"(b[1]));
}
__device__ __forceinline__ void mma_fp(float* c, const uint32_t* a, const uint32_t* b) {
    asm volatile(
        "mma.sync.aligned.m16n8k16.row.col.f32.f16.f16.f32 "
        "{%0,%1,%2,%3}, {%4,%5,%6,%7}, {%8,%9}, {%0,%1,%2,%3};"
        : "+f"(c[0]), "+f"(c[1]), "+f"(c[2]), "+f"(c[3])
        : "r"(a[0]), "r"(a[1]), "r"(a[2]), "r"(a[3]), "r"(b[0]), "r"(b[1]));
}

// ============================================================================
// Conversion kernels
// ============================================================================
__global__ void split_bf(const float* __restrict__ src,
                         bf16* __restrict__ hi, bf16* __restrict__ lo)
{
    size_t i = ((size_t)blockIdx.x * 256 + threadIdx.x) * 4;
    float4 v = *(const float4*)(src + i);
    union { bf16 h[4]; uint2 u; } H, L;
    float vv[4] = {v.x, v.y, v.z, v.w};
    #pragma unroll
    for (int j = 0; j < 4; j++) {
        bf16 h = __float2bfloat16_rn(vv[j]);
        H.h[j] = h;
        L.h[j] = __float2bfloat16_rn(vv[j] - __bfloat162float(h));
    }
    *(uint2*)(hi + i) = H.u;
    *(uint2*)(lo + i) = L.u;
}

__global__ void split_gather_bf(const float* __restrict__ emb, const int* __restrict__ tok,
                                bf16* __restrict__ hi, bf16* __restrict__ lo)
{
    int m = blockIdx.x;
    int row = tok[m];
    size_t s = (size_t)row * H_ + threadIdx.x * 4;
    size_t d = (size_t)m * H_ + threadIdx.x * 4;
    float4 v = *(const float4*)(emb + s);
    union { bf16 h[4]; uint2 u; } H, L;
    float vv[4] = {v.x, v.y, v.z, v.w};
    #pragma unroll
    for (int j = 0; j < 4; j++) {
        bf16 h = __float2bfloat16_rn(vv[j]);
        H.h[j] = h;
        L.h[j] = __float2bfloat16_rn(vv[j] - __bfloat162float(h));
    }
    *(uint2*)(hi + d) = H.u;
    *(uint2*)(lo + d) = L.u;
}

__global__ void conv_f16(const float* __restrict__ src, half* __restrict__ dst)
{
    size_t i = ((size_t)blockIdx.x * 256 + threadIdx.x) * 8;
    float4 v0 = *(const float4*)(src + i);
    float4 v1 = *(const float4*)(src + i + 4);
    union { half h[8]; uint4 u; } O;
    O.h[0] = __float2half_rn(v0.x); O.h[1] = __float2half_rn(v0.y);
    O.h[2] = __float2half_rn(v0.z); O.h[3] = __float2half_rn(v0.w);
    O.h[4] = __float2half_rn(v1.x); O.h[5] = __float2half_rn(v1.y);
    O.h[6] = __float2half_rn(v1.z); O.h[7] = __float2half_rn(v1.w);
    *(uint4*)(dst + i) = O.u;
}

// ============================================================================
// Shared GEMM pieces: 128x128 tile, K-chunk 32, row = 64 B of 16-bit elems
// ============================================================================
__device__ __forceinline__ uint32_t sw_addr(uint32_t tile, int row, int chunk) {
    return tile + (uint32_t)row * 64u + (uint32_t)((chunk ^ ((row >> 1) & 3)) * 16);
}
#define TILE_B 8192u
#define NCC 32

// ---------------- bf16 3-term projection GEMM (1 CTA/SM) ----------------
#define STG3_B  (4u * TILE_B)
#define NSTG3 3
#define MMA3_SMEM (NSTG3 * STG3_B)

__device__ __forceinline__ void load_chunk3(
    uint32_t stg, const bf16* __restrict__ Ahi, const bf16* __restrict__ Alo,
    const bf16* __restrict__ Bhi, const bf16* __restrict__ Blo,
    int m0, int n0, int kc, int tid)
{
    const int koff = kc * 32;
    #pragma unroll
    for (int j = 0; j < 8; j++) {
        int idx = tid + j * 256;
        int tile = idx >> 9;
        int rem = idx & 511;
        int r = rem >> 2, c = rem & 3;
        const bf16* src;
        int grow;
        if (tile == 0)      { src = Ahi; grow = m0 + r; }
        else if (tile == 1) { src = Alo; grow = m0 + r; }
        else if (tile == 2) { src = Bhi; grow = n0 + r; }
        else                { src = Blo; grow = n0 + r; }
        cpa16(sw_addr(stg + (uint32_t)tile * TILE_B, r, c),
              src + (size_t)grow * H_ + koff + c * 8);
    }
    CP_COMMIT();
}

__global__ void __launch_bounds__(256, 1) mma_gemm3(
    const bf16* __restrict__ Ahi, const bf16* __restrict__ Alo,
    const bf16* __restrict__ Bhi, const bf16* __restrict__ Blo,
    const float* __restrict__ bias1, const float* __restrict__ bias2,
    float* __restrict__ C, int ldn)
{
    extern __shared__ char smc[];
    const uint32_t smb = smem_u32(smc);
    const int tid = threadIdx.x;
    const int wid = tid >> 5, lid = tid & 31;
    const int wm = wid >> 2, wn = wid & 3;
    const int m0 = blockIdx.x * 128;
    const int n0 = blockIdx.y * 128;

    float acc[4][4][4];
    #pragma unroll
    for (int i = 0; i < 4; i++)
        #pragma unroll
        for (int j = 0; j < 4; j++)
            #pragma unroll
            for (int q = 0; q < 4; q++) acc[i][j][q] = 0.0f;

    const int l7 = lid & 7;
    const int lb8 = (lid >> 3) & 1;
    const int lb16 = lid >> 4;
    const int lm = lid >> 3;

    load_chunk3(smb,          Ahi, Alo, Bhi, Blo, m0, n0, 0, tid);
    load_chunk3(smb + STG3_B, Ahi, Alo, Bhi, Blo, m0, n0, 1, tid);

    for (int i = 0; i < NCC; i++) {
        if (i < NCC - 1) { CP_WAIT1(); } else { CP_WAIT0(); }
        __syncthreads();

        const uint32_t stg = smb + (uint32_t)(i % NSTG3) * STG3_B;
        const uint32_t tAhi = stg, tAlo = stg + TILE_B;
        const uint32_t tBhi = stg + 2 * TILE_B, tBlo = stg + 3 * TILE_B;

        #pragma unroll
        for (int ks = 0; ks < 2; ks++) {
            uint32_t ahi[4][4], alo[4][4], bhi[4][2], blo[4][2];
            const int ach = ks * 2 + lb16;
            #pragma unroll
            for (int mi = 0; mi < 4; mi++) {
                int row = wm * 64 + mi * 16 + l7 + lb8 * 8;
                ldsm4(ahi[mi][0], ahi[mi][1], ahi[mi][2], ahi[mi][3], sw_addr(tAhi, row, ach));
                ldsm4(alo[mi][0], alo[mi][1], alo[mi][2], alo[mi][3], sw_addr(tAlo, row, ach));
            }
            const int bch = ks * 2 + (lm & 1);
            #pragma unroll
            for (int p = 0; p < 2; p++) {
                int row = wn * 32 + p * 16 + l7 + ((lm >= 2) ? 8 : 0);
                uint32_t r0, r1, r2, r3;
                ldsm4(r0, r1, r2, r3, sw_addr(tBhi, row, bch));
                bhi[2*p][0] = r0; bhi[2*p][1] = r1; bhi[2*p+1][0] = r2; bhi[2*p+1][1] = r3;
                ldsm4(r0, r1, r2, r3, sw_addr(tBlo, row, bch));
                blo[2*p][0] = r0; blo[2*p][1] = r1; blo[2*p+1][0] = r2; blo[2*p+1][1] = r3;
            }
            #pragma unroll
            for (int mi = 0; mi < 4; mi++)
                #pragma unroll
                for (int nj = 0; nj < 4; nj++) {
                    mma_bf(acc[mi][nj], ahi[mi], bhi[nj]);
                    mma_bf(acc[mi][nj], alo[mi], bhi[nj]);
                    mma_bf(acc[mi][nj], ahi[mi], blo[nj]);
                }
        }

        if (i + 2 < NCC)
            load_chunk3(smb + (uint32_t)((i + 2) % NSTG3) * STG3_B,
                        Ahi, Alo, Bhi, Blo, m0, n0, i + 2, tid);
    }

    const int gid = lid >> 2, tig = lid & 3;
    #pragma unroll
    for (int nj = 0; nj < 4; nj++) {
        const int col = n0 + wn * 32 + nj * 8 + tig * 2;
        float2 bv;
        bv.x = bias1[col]; bv.y = bias1[col + 1];
        if (bias2) { bv.x += bias2[col]; bv.y += bias2[col + 1]; }
        #pragma unroll
        for (int mi = 0; mi < 4; mi++) {
            const int r0 = m0 + wm * 64 + mi * 16 + gid;
            float2 v0 = {acc[mi][nj][0] + bv.x, acc[mi][nj][1] + bv.y};
            float2 v1 = {acc[mi][nj][2] + bv.x, acc[mi][nj][3] + bv.y};
            *(float2*)(C + (size_t)r0 * ldn + col) = v0;
            *(float2*)(C + (size_t)(r0 + 8) * ldn + col) = v1;
        }
    }
}

// ---------------- fp16 single-term output GEMM (2 CTAs/SM, 4 stages) ----------
#define STG1_B  (2u * TILE_B)      // Ah, Bh = 16 KB
#define NSTG1 4
#define MMA1_SMEM (NSTG1 * STG1_B) // 64 KB

__device__ __forceinline__ void load_chunk1(
    uint32_t stg, const half* __restrict__ Ah, const half* __restrict__ Bh,
    int m0, int n0, int kc, int tid)
{
    const int koff = kc * 32;
    #pragma unroll
    for (int j = 0; j < 4; j++) {
        int idx = tid + j * 256;
        int tile = idx >> 9;               // 0:Ah 1:Bh
        int rem = idx & 511;
        int r = rem >> 2, c = rem & 3;
        const half* src = tile ? Bh : Ah;
        int grow = (tile ? n0 : m0) + r;
        cpa16(sw_addr(stg + (uint32_t)tile * TILE_B, r, c),
              src + (size_t)grow * H_ + koff + c * 8);
    }
    CP_COMMIT();
}

__global__ void __launch_bounds__(256, 2) mma_gemm1(
    const half* __restrict__ Ah, const half* __restrict__ Bh,
    const float* __restrict__ bias1,
    float* __restrict__ C, int ldn, float* __restrict__ lastout)
{
    extern __shared__ char smc[];
    const uint32_t smb = smem_u32(smc);
    const int tid = threadIdx.x;
    const int wid = tid >> 5, lid = tid & 31;
    const int wm = wid >> 2, wn = wid & 3;
    const int m0 = blockIdx.x * 128;
    const int n0 = blockIdx.y * 128;

    float acc[4][4][4];
    #pragma unroll
    for (int i = 0; i < 4; i++)
        #pragma unroll
        for (int j = 0; j < 4; j++)
            #pragma unroll
            for (int q = 0; q < 4; q++) acc[i][j][q] = 0.0f;

    const int l7 = lid & 7;
    const int lb8 = (lid >> 3) & 1;
    const int lb16 = lid >> 4;
    const int lm = lid >> 3;

    // prologue: chunks 0..2 into stages 0..2
    load_chunk1(smb,              Ah, Bh, m0, n0, 0, tid);
    load_chunk1(smb + STG1_B,     Ah, Bh, m0, n0, 1, tid);
    load_chunk1(smb + 2 * STG1_B, Ah, Bh, m0, n0, 2, tid);

    for (int i = 0; i < NCC; i++) {
        if (i + 3 < NCC) {
            load_chunk1(smb + (uint32_t)((i + 3) % NSTG1) * STG1_B,
                        Ah, Bh, m0, n0, i + 3, tid);
            CP_WAIT3();
        } else if (i + 2 < NCC) { CP_WAIT2(); }
        else if (i + 1 < NCC)   { CP_WAIT1(); }
        else                    { CP_WAIT0(); }
        __syncthreads();

        const uint32_t stg = smb + (uint32_t)(i % NSTG1) * STG1_B;
        const uint32_t tAh = stg, tBh = stg + TILE_B;

        #pragma unroll
        for (int ks = 0; ks < 2; ks++) {
            uint32_t a[4][4], bh[4][2];
            const int ach = ks * 2 + lb16;
            const int bch = ks * 2 + (lm & 1);
            #pragma unroll
            for (int p = 0; p < 2; p++) {
                int row = wn * 32 + p * 16 + l7 + ((lm >= 2) ? 8 : 0);
                uint32_t r0, r1, r2, r3;
                ldsm4(r0, r1, r2, r3, sw_addr(tBh, row, bch));
                bh[2*p][0] = r0; bh[2*p][1] = r1; bh[2*p+1][0] = r2; bh[2*p+1][1] = r3;
            }
            #pragma unroll
            for (int mi = 0; mi < 4; mi++) {
                int row = wm * 64 + mi * 16 + l7 + lb8 * 8;
                ldsm4(a[mi][0], a[mi][1], a[mi][2], a[mi][3], sw_addr(tAh, row, ach));
            }
            #pragma unroll
            for (int mi = 0; mi < 4; mi++)
                #pragma unroll
                for (int nj = 0; nj < 4; nj++)
                    mma_fp(acc[mi][nj], a[mi], bh[nj]);
        }
        __syncthreads();
    }

    const int gid = lid >> 2, tig = lid & 3;
    #pragma unroll
    for (int nj = 0; nj < 4; nj++) {
        const int col = n0 + wn * 32 + nj * 8 + tig * 2;
        float2 bv;
        bv.x = bias1[col]; bv.y = bias1[col + 1];
        #pragma unroll
        for (int mi = 0; mi < 4; mi++) {
            const int r0 = m0 + wm * 64 + mi * 16 + gid;
            float2 v0 = {acc[mi][nj][0] + bv.x, acc[mi][nj][1] + bv.y};
            float2 v1 = {acc[mi][nj][2] + bv.x, acc[mi][nj][3] + bv.y};
            *(float2*)(C + (size_t)r0 * ldn + col) = v0;
            *(float2*)(C + (size_t)(r0 + 8) * ldn + col) = v1;
            if (lastout && ((r0 + 8) & 127) == 127)
                *(float2*)(lastout + (size_t)blockIdx.x * ldn + col) = v1;
        }
    }
}

// ============================================================================
// Fused 2-layer wavefront recurrence. 129 supersteps, 128 CTAs x 256 threads.
// Superstep s computes h0[s] (s<128) and h1[s-1] (s>=1):
//   h0[s]   = tanh(xw0[:,s,:]   + h0[s-1] @ Whh0^T)      (xw0 incl. biases)
//   h1[s-1] = tanh(h0[s-1] @ Wih1^T + h1[s-2] @ Whh1^T + bih1 + bhh1)
// h staged via cp.async into two ping-pong half-buffers [32][516] (R11 decode).
// W slices (3 x 8 rows, 1028-pad) in smem. Guarded writes keep flow uniform.
// ============================================================================
#define NB 128
#define SBS 516                                  // staged half-buffer row stride
#define WS  1028                                 // W row stride
#define FUSED_SMEM ((2 * 32 * SBS + 3 * 8 * WS + 8 * 33) * 4)   // 231,840 B

__device__ __forceinline__ void stage_half(uint32_t dstb, const float* __restrict__ src,
                                           int jh, int tid) {
    const float* s = src + jh * 512;
    #pragma unroll
    for (int q = 0; q < 16; q++) {
        int ci = tid + q * 256;                  // [0,4096): 32 rows x 128 chunks
        int r = ci >> 7, c = ci & 127;
        cpa16(dstb + (uint32_t)(r * (SBS * 4) + c * 16), s + r * H_ + c * 4);
    }
    CP_COMMIT();
}

// dual-dot half: acc0 += w0·h, acc1 += w1·h over 512 elements
__device__ __forceinline__ void dot2_half(
    const float* __restrict__ hrow, const float* __restrict__ w0p,
    const float* __restrict__ w1p, ull& a00, ull& a01, ull& a10, ull& a11)
{
    #pragma unroll 4
    for (int j = 0; j < 512; j += 8) {
        ulonglong2 hq0 = *(const ulonglong2*)(hrow + j);
        ulonglong2 hq1 = *(const ulonglong2*)(hrow + j + 4);
        ulonglong2 wa0 = *(const ulonglong2*)(w0p + j);
        ulonglong2 wa1 = *(const ulonglong2*)(w0p + j + 4);
        ulonglong2 wb0 = *(const ulonglong2*)(w1p + j);
        ulonglong2 wb1 = *(const ulonglong2*)(w1p + j + 4);
        ffma2(a00, hq0.x, wa0.x); ffma2(a01, hq0.y, wa0.y);
        ffma2(a00, hq1.x, wa1.x); ffma2(a01, hq1.y, wa1.y);
        ffma2(a10, hq0.x, wb0.x); ffma2(a11, hq0.y, wb0.y);
        ffma2(a10, hq1.x, wb1.x); ffma2(a11, hq1.y, wb1.y);
    }
}

// single-dot half: acc += w·h over 512 elements
__device__ __forceinline__ void dot1_half(
    const float* __restrict__ hrow, const float* __restrict__ wp, ull& a0, ull& a1)
{
    #pragma unroll 8
    for (int j = 0; j < 512; j += 4) {
        ulonglong2 hq = *(const ulonglong2*)(hrow + j);
        ulonglong2 wq = *(const ulonglong2*)(wp + j);
        ffma2(a0, hq.x, wq.x);
        ffma2(a1, hq.y, wq.y);
    }
}

__global__ void __launch_bounds__(256, 1) rnn_fused(
    const float* __restrict__ xw0, const float* __restrict__ Whh0,
    const float* __restrict__ Wih1, const float* __restrict__ Whh1,
    const float* __restrict__ bih1, const float* __restrict__ bhh1,
    const float* __restrict__ hinit,    // [2][B][H]
    float* __restrict__ y1,             // [B][T][H]
    float* __restrict__ hfin)           // [2][B][H]
{
    extern __shared__ float smf[];
    float* buf0  = smf;                          // [32][SBS]
    float* buf1  = smf + 32 * SBS;               // [32][SBS]
    float* w0_s  = smf + 2 * 32 * SBS;           // [8][WS]
    float* wi1_s = w0_s + 8 * WS;
    float* wh1_s = wi1_s + 8 * WS;
    float* hv_s  = wh1_s + 8 * WS;               // [8][33]

    const int tid = threadIdx.x;
    const int blk = blockIdx.x;
    const int wrp = tid >> 5, lane = tid & 31;
    const int i_loc = lane >> 2;
    const int b = wrp * 4 + (lane & 3);
    const int i = blk * 8 + i_loc;

    // stage W slices (8 rows x 3 matrices)
    #pragma unroll
    for (int q = 0; q < 8; q++) {
        int fi = tid + q * 256;
        int r = fi >> 8, c = (fi & 255) * 4;
        *(float4*)&w0_s[r * WS + c]  = *(const float4*)&Whh0[(size_t)(blk * 8 + r) * H_ + c];
        *(float4*)&wi1_s[r * WS + c] = *(const float4*)&Wih1[(size_t)(blk * 8 + r) * H_ + c];
        *(float4*)&wh1_s[r * WS + c] = *(const float4*)&Whh1[(size_t)(blk * 8 + r) * H_ + c];
    }
    // init hidden double buffers: h0[-1] -> idx 1, h1[-1] -> idx 1
    g_h0buf[1][blk * 256 + tid] = hinit[blk * 256 + tid];
    g_h1buf[1][blk * 256 + tid] = hinit[B_ * H_ + blk * 256 + tid];

    const float b1v = bih1[i] + bhh1[i];

    // ---- init barrier (proven R11/R15 scheme) + recover counter base ----
    ull base = 0;
    __syncthreads();
    if (tid == 0) {
        __threadfence();
        ull a = atomicAdd(&g_acnt, 1ULL) + 1ULL;
        ull tgt = (a + NB - 1) / NB;
        if (a == tgt * NB) {
            atomicExch(&g_gen, tgt);
        } else {
            while (*((volatile ull*)&g_gen) < tgt) { __nanosleep(64); }
        }
        __threadfence();
        base = tgt * NB;
    }
    __syncthreads();

    const uint32_t b0_sb = smem_u32(buf0);
    const uint32_t b1_sb = smem_u32(buf1);
    const float* r0 = buf0 + b * SBS;
    const float* r1 = buf1 + b * SBS;
    const float* w0row  = w0_s  + i_loc * WS;
    const float* wi1row = wi1_s + i_loc * WS;
    const float* wh1row = wh1_s + i_loc * WS;

    for (int s = 0; s <= T_; s++) {
        const float* h0prev = g_h0buf[(s + 1) & 1];   // h0[s-1]
        const float* h1prev = g_h1buf[s & 1];         // h1[s-2]

        // stage h0[s-1]: lo -> buf0 (g1), hi -> buf1 (g2)
        stage_half(b0_sb, h0prev, 0, tid);
        stage_half(b1_sb, h0prev, 1, tid);

        const int t0 = (s < T_) ? s : (T_ - 1);
        float xv0 = xw0[((size_t)b * T_ + t0) * H_ + i];

        ull a00 = 0, a01 = 0, a10 = 0, a11 = 0;
        CP_WAIT1();                                   // g1 done (g2 may pend)
        __syncthreads();
        dot2_half(r0, w0row, wi1row, a00, a01, a10, a11);       // h0 lo
        __syncthreads();                              // buf0 fully consumed
        stage_half(b0_sb, h1prev, 0, tid);            // g3: h1[s-2] lo -> buf0
        CP_WAIT1();                                   // g2 done (g3 may pend)
        __syncthreads();
        dot2_half(r1, w0row + 512, wi1row + 512, a00, a01, a10, a11);   // h0 hi

        // layer-0 output
        {
            float2 f0 = unpack2(a00), f1 = unpack2(a01);
            float h0v = tanhf((f0.x + f0.y) + (f1.x + f1.y) + xv0);
            hv_s[i_loc * 33 + b] = h0v;
        }
        __syncthreads();
        {
            int bb = tid >> 3, io = tid & 7;
            float v = hv_s[io * 33 + bb];
            if (s < T_) {
                g_h0buf[s & 1][bb * H_ + blk * 8 + io] = v;
                if (s == T_ - 1) hfin[bb * H_ + blk * 8 + io] = v;
            }
        }
        __syncthreads();                              // buf1 + hv_s consumed
        stage_half(b1_sb, h1prev, 1, tid);            // g4: h1[s-2] hi -> buf1

        CP_WAIT1();                                   // g3 done (g4 may pend)
        __syncthreads();
        dot1_half(r0, wh1row, a10, a11);              // h1 lo
        CP_WAIT0();                                   // g4 done
        __syncthreads();
        dot1_half(r1, wh1row + 512, a10, a11);        // h1 hi

        // layer-1 output
        {
            float2 f0 = unpack2(a10), f1 = unpack2(a11);
            float h1v = tanhf((f0.x + f0.y) + (f1.x + f1.y) + b1v);
            hv_s[i_loc * 33 + b] = h1v;
        }
        __syncthreads();
        {
            int bb = tid >> 3, io = tid & 7;
            float v = hv_s[io * 33 + bb];
            if (s >= 1) {
                g_h1buf[(s - 1) & 1][bb * H_ + blk * 8 + io] = v;
                y1[((size_t)bb * T_ + (s - 1)) * H_ + blk * 8 + io] = v;
                if (s - 1 == T_ - 1) hfin[B_ * H_ + bb * H_ + blk * 8 + io] = v;
            }
        }

        // ---- step barrier: red arrivals + monotonic counter poll ----
        __syncthreads();
        if (tid == 0) {
            __threadfence();
            asm volatile("red.global.add.u64 [%0], %1;"
                         :: "l"(&g_acnt), "l"(1ULL) : "memory");
            ull target = base + (ull)(s + 1) * NB;
            while (__ldcg(&g_acnt) < target) { __nanosleep(32); }
            __threadfence();
        }
        __syncthreads();
    }
}

// ============================================================================
extern "C" void kernel_launch(void* const* d_in, const int* in_sizes, int n_in,
                              void* d_out, int out_size)
{
    const int*   tok  = (const int*)  d_in[0];
    const float* hid  = (const float*)d_in[1];
    const float* emb  = (const float*)d_in[2];
    const float* Wih0 = (const float*)d_in[3];
    const float* Whh0 = (const float*)d_in[4];
    const float* bih0 = (const float*)d_in[5];
    const float* bhh0 = (const float*)d_in[6];
    const float* Wih1 = (const float*)d_in[7];
    const float* Whh1 = (const float*)d_in[8];
    const float* bih1 = (const float*)d_in[9];
    const float* bhh1 = (const float*)d_in[10];
    const float* Wout = (const float*)d_in[11];
    const float* bout = (const float*)d_in[12];
    float* out = (float*)d_out;

    float *bufA, *bufB;
    bf16 *Ahi, *Alo, *Phi, *Plo;
    half *Wh16, *Ah16;
    cudaGetSymbolAddress((void**)&bufA, g_bufA);
    cudaGetSymbolAddress((void**)&bufB, g_bufB);
    cudaGetSymbolAddress((void**)&Ahi, g_Ahi);
    cudaGetSymbolAddress((void**)&Alo, g_Alo);
    cudaGetSymbolAddress((void**)&Phi, g_Phi);
    cudaGetSymbolAddress((void**)&Plo, g_Plo);
    cudaGetSymbolAddress((void**)&Wh16, g_Wh16);
    cudaGetSymbolAddress((void**)&Ah16, g_Ah16);

    cudaFuncSetAttribute(mma_gemm3, cudaFuncAttributeMaxDynamicSharedMemorySize, MMA3_SMEM);
    cudaFuncSetAttribute(mma_gemm1, cudaFuncAttributeMaxDynamicSharedMemorySize, MMA1_SMEM);
    cudaFuncSetAttribute(rnn_fused, cudaFuncAttributeMaxDynamicSharedMemorySize, FUSED_SMEM);

    // W_out -> fp16
    conv_f16<<<(int)((size_t)V_ * H_ / 2048), 256>>>(Wout, Wh16);

    // layer-0 input projection: xw0 = emb[tok] @ Wih0^T + (bih0+bhh0)
    split_gather_bf<<<M_, 256>>>(emb, tok, Ahi, Alo);
    split_bf<<<(int)((size_t)H_ * H_ / 1024), 256>>>(Wih0, Phi, Plo);
    mma_gemm3<<<dim3(M_ / 128, H_ / 128), 256, MMA3_SMEM>>>(
        Ahi, Alo, Phi, Plo, bih0, bhh0, bufA, H_);

    // fused 2-layer recurrence (y1 -> bufB, finals -> out[OUT_HID..])
    rnn_fused<<<NB, 256, FUSED_SMEM>>>(
        bufA, Whh0, Wih1, Whh1, bih1, bhh1, hid, bufB, out + OUT_HID);

    // output projection: fp16 single-term, last_output fused
    conv_f16<<<(int)((size_t)M_ * H_ / 2048), 256>>>(bufB, Ah16);
    mma_gemm1<<<dim3(M_ / 128, V_ / 128), 256, MMA1_SMEM>>>(
        Ah16, Wh16, bout, out, V_, out + OUT_LAST);
}